// round 8
// baseline (speedup 1.0000x reference)
#include <cuda_runtime.h>
#include <cuda_bf16.h>
#include <cstdint>
#include <cstddef>

#define HW    10000
#define WID   100
#define NPAD  10240
#define KTOT  2304
#define WROWS 3584
#define SLOTS 6
#define CSTR  ((size_t)NPAD * KTOT)   // col-slot stride (elements)
#define FSTR  ((size_t)256 * HW)      // feature-chain stride

typedef __nv_bfloat16 bf16;

__device__ bf16 g_wh[WROWS * KTOT];              // 16.5 MB
__device__ bf16 g_wl[WROWS * KTOT];
__device__ bf16 g_colh[SLOTS * CSTR];            // 283 MB
__device__ bf16 g_coll[SLOTS * CSTR];
__device__ bf16 g_cth[2 * CSTR];                 // cls cat (94 MB)
__device__ bf16 g_ctl[2 * CSTR];
__device__ bf16 g_crh[2 * CSTR];                 // reg cat
__device__ bf16 g_crl[2 * CSTR];
__device__ float g_ftA[4 * 256 * HW];            // tower ping
__device__ float g_ftB[4 * 256 * HW];            // tower pong (final: cf0,rf0,cf1,rf1)
__device__ float g_boxreg[2 * 36 * HW];
__device__ float g_refine[2 * 36 * HW];

__constant__ float c_AW[9] = {
    2.8284271247461903f, 2.0f, 1.4142135623730951f,
    3.5635948725613580f, 2.5198420997897464f, 1.7817974362806790f,
    4.4898481932374910f, 3.1748021039363988f, 2.2449240966187455f};
__constant__ float c_AH[9] = {
    1.4142135623730951f, 2.0f, 2.8284271247461903f,
    1.7817974362806790f, 2.5198420997897464f, 3.5635948725613580f,
    2.2449240966187455f, 3.1748021039363988f, 4.4898481932374910f};

__device__ __forceinline__ uint32_t smem_u32(const void* p) {
    uint32_t a;
    asm("{ .reg .u64 t; cvta.to.shared.u64 t, %1; cvt.u32.u64 %0, t; }" : "=r"(a) : "l"(p));
    return a;
}
__device__ __forceinline__ void cp16(uint32_t dst, const void* src) {
    asm volatile("cp.async.cg.shared.global [%0], [%1], 16;" :: "r"(dst), "l"(src));
}
__device__ __forceinline__ void ldmx4(uint32_t* r, uint32_t addr) {
    asm volatile("ldmatrix.sync.aligned.m8n8.x4.shared.b16 {%0,%1,%2,%3}, [%4];"
                 : "=r"(r[0]), "=r"(r[1]), "=r"(r[2]), "=r"(r[3]) : "r"(addr));
}
__device__ __forceinline__ void mma16816(float* c, const uint32_t* a, uint32_t b0, uint32_t b1) {
    asm volatile("mma.sync.aligned.m16n8k16.row.col.f32.bf16.bf16.f32 "
                 "{%0,%1,%2,%3}, {%4,%5,%6,%7}, {%8,%9}, {%0,%1,%2,%3};"
                 : "+f"(c[0]), "+f"(c[1]), "+f"(c[2]), "+f"(c[3])
                 : "r"(a[0]), "r"(a[1]), "r"(a[2]), "r"(a[3]), "r"(b0), "r"(b1));
}
__device__ __forceinline__ uint32_t bpack(bf16 a, bf16 b) {
    return (uint32_t)__bfloat16_as_ushort(a) | ((uint32_t)__bfloat16_as_ushort(b) << 16);
}
// smem tile: 128 rows x 8 chunks of 16B (128B/row = BK 64 bf16), XOR-8 swizzle
__device__ __forceinline__ uint32_t sw_off(int r, int c) {
    return (uint32_t)((r * 8 + (c ^ (r & 7))) << 4);
}

#define TILE_B 16384
#define STAGE_B (4 * TILE_B)
#define NSTG 3
#define NK   36
#define SMEM_SZ (NSTG * STAGE_B)

// flags: 1=bias 2=relu 4=cat-out 8=tower(z-indexed A/bias)
__global__ __launch_bounds__(256) void mma_gemm(
    const bf16* __restrict__ Ah0, const bf16* __restrict__ Al0, int arowE, int arowO,
    const bf16* __restrict__ Bh0, const bf16* __restrict__ Bl0,
    const float* __restrict__ biasE, const float* __restrict__ biasO,
    float* __restrict__ outF, size_t outStride,
    bf16* __restrict__ outTh, bf16* __restrict__ outTl,
    int M, int flags, int zoff)
{
    extern __shared__ char smem[];
    const uint32_t sb = smem_u32(smem);
    const int tid = threadIdx.x, lane = tid & 31, w = tid >> 5;
    const int wm = w >> 2, wn = w & 3;
    const int m0 = blockIdx.y * 128, n0 = blockIdx.x * 128;
    const int zl = blockIdx.z;          // local z (col slot)
    const int z = zl + zoff;            // global z (cat / out index)

    const bool odd = (flags & 8) && (z & 1);
    const int arow = odd ? arowO : arowE;
    const float* bias = odd ? biasO : biasE;

    const bf16* srcs[4] = {
        Ah0 + ((size_t)arow + m0) * KTOT, Al0 + ((size_t)arow + m0) * KTOT,
        Bh0 + (size_t)zl * CSTR + (size_t)n0 * KTOT,
        Bl0 + (size_t)zl * CSTR + (size_t)n0 * KTOT};

    float acc[4][4][4];
#pragma unroll
    for (int i = 0; i < 4; i++)
#pragma unroll
        for (int j = 0; j < 4; j++)
#pragma unroll
            for (int q = 0; q < 4; q++) acc[i][j][q] = 0.f;

    const int ra = (lane & 15);
    const int ca = lane >> 4;
    const int rb = (lane & 7) + ((lane >> 4) << 3);
    const int cb = (lane >> 3) & 1;

    // one stage = 4 tiles x 128 rows x 8 chunks(16B) ; 16 cp16/thread
#define LOAD_STAGE(s, k0) do { \
    _Pragma("unroll") \
    for (int t = 0; t < 4; t++) { \
        const uint32_t base = sb + (uint32_t)((s) * STAGE_B + t * TILE_B); \
        _Pragma("unroll") \
        for (int h = 0; h < 4; h++) { \
            const int q = tid + h * 256; \
            const int r = q >> 3, c = q & 7; \
            cp16(base + sw_off(r, c), srcs[t] + (size_t)r * KTOT + (k0) + c * 8); \
        } \
    } \
} while (0)

    LOAD_STAGE(0, 0);
    asm volatile("cp.async.commit_group;" ::: "memory");
    LOAD_STAGE(1, 64);
    asm volatile("cp.async.commit_group;" ::: "memory");

    for (int kc = 0; kc < NK; kc++) {
        asm volatile("cp.async.wait_group 1;" ::: "memory");
        __syncthreads();

        const uint32_t bA  = sb + (uint32_t)((kc % NSTG) * STAGE_B);
        const uint32_t bAl = bA + TILE_B;
        const uint32_t bBh = bA + 2 * TILE_B;
        const uint32_t bBl = bA + 3 * TILE_B;
#pragma unroll
        for (int kh = 0; kh < 4; kh++) {
            uint32_t fbh[2][4], fbl[2][4];
#pragma unroll
            for (int nt2 = 0; nt2 < 2; nt2++) {
                const int rr = wn * 32 + nt2 * 16 + rb;
                const int cc = kh * 2 + cb;
                ldmx4(fbh[nt2], bBh + sw_off(rr, cc));
                ldmx4(fbl[nt2], bBl + sw_off(rr, cc));
            }
#pragma unroll
            for (int mt = 0; mt < 4; mt++) {
                uint32_t fah[4], fal[4];
                const int rr = wm * 64 + mt * 16 + ra;
                const int cc = kh * 2 + ca;
                ldmx4(fah, bA  + sw_off(rr, cc));
                ldmx4(fal, bAl + sw_off(rr, cc));
#pragma unroll
                for (int nt = 0; nt < 4; nt++) {
                    const uint32_t b0h = fbh[nt >> 1][(nt & 1) * 2];
                    const uint32_t b1h = fbh[nt >> 1][(nt & 1) * 2 + 1];
                    const uint32_t b0l = fbl[nt >> 1][(nt & 1) * 2];
                    const uint32_t b1l = fbl[nt >> 1][(nt & 1) * 2 + 1];
                    mma16816(acc[mt][nt], fah, b0h, b1h);
                    mma16816(acc[mt][nt], fah, b0l, b1l);
                    mma16816(acc[mt][nt], fal, b0h, b1h);
                }
            }
        }
        // prefetch chunk kc+2 into slot (kc+2)%3 (safe: one sync behind)
        if (kc + 2 < NK) LOAD_STAGE((kc + 2) % NSTG, (kc + 2) * 64);
        asm volatile("cp.async.commit_group;" ::: "memory");
    }
    __syncthreads();

    const int group = lane >> 2, tid4 = lane & 3;

    if (flags & 4) {
        // global z = bpp*9 + ap ; transpose through smem, write bf16 hi/lo cat
        const int bpp = z / 9, ap = z % 9;
        float* smf = (float*)smem;
#pragma unroll
        for (int mt = 0; mt < 4; mt++) {
#pragma unroll
            for (int nt = 0; nt < 4; nt++) {
                const int ml = wm * 64 + mt * 16 + group;
                const int nl = wn * 32 + nt * 8 + tid4 * 2;
                smf[nl * 128 + ml]           = acc[mt][nt][0];
                smf[(nl + 1) * 128 + ml]     = acc[mt][nt][1];
                smf[nl * 128 + ml + 8]       = acc[mt][nt][2];
                smf[(nl + 1) * 128 + ml + 8] = acc[mt][nt][3];
            }
        }
        __syncthreads();
        const int nl = tid >> 1, half = tid & 1;
        const size_t row_out = (size_t)(bpp * NPAD + n0 + nl) * KTOT + ap * 256 + m0 + half * 64;
        const float* row = smf + nl * 128 + half * 64;
        bf16* oh = outTh + row_out;
        bf16* ol = outTl + row_out;
#pragma unroll
        for (int g = 0; g < 8; g++) {
            bf16 hs[8], ls[8];
#pragma unroll
            for (int j = 0; j < 8; j++) {
                const float v = fmaxf(row[g * 8 + j], 0.f);
                hs[j] = __float2bfloat16(v);
                ls[j] = __float2bfloat16(v - __bfloat162float(hs[j]));
            }
            *(uint4*)(oh + g * 8) = make_uint4(bpack(hs[0],hs[1]), bpack(hs[2],hs[3]),
                                               bpack(hs[4],hs[5]), bpack(hs[6],hs[7]));
            *(uint4*)(ol + g * 8) = make_uint4(bpack(ls[0],ls[1]), bpack(ls[2],ls[3]),
                                               bpack(ls[4],ls[5]), bpack(ls[6],ls[7]));
        }
    } else {
        float* oF = outF + (size_t)z * outStride;
#pragma unroll
        for (int mt = 0; mt < 4; mt++) {
            const int mA = m0 + wm * 64 + mt * 16 + group;
            const int mB = mA + 8;
            const float bvA = ((flags & 1) && mA < M) ? bias[mA] : 0.f;
            const float bvB = ((flags & 1) && mB < M) ? bias[mB] : 0.f;
#pragma unroll
            for (int nt = 0; nt < 4; nt++) {
                const int n = n0 + wn * 32 + nt * 8 + tid4 * 2;
#pragma unroll
                for (int e = 0; e < 2; e++) {
                    if (n + e < HW) {
                        if (mA < M) {
                            float v = acc[mt][nt][e] + bvA;
                            if (flags & 2) v = fmaxf(v, 0.f);
                            oF[(size_t)mA * HW + n + e] = v;
                        }
                        if (mB < M) {
                            float v = acc[mt][nt][2 + e] + bvB;
                            if (flags & 2) v = fmaxf(v, 0.f);
                            oF[(size_t)mB * HW + n + e] = v;
                        }
                    }
                }
            }
        }
    }
#undef LOAD_STAGE
}

__global__ void wsplit_kernel(const float* __restrict__ src, bf16* __restrict__ h,
                              bf16* __restrict__ l, int M, int Mp)
{
    const int idx = blockIdx.x * blockDim.x + threadIdx.x;
    if (idx >= Mp * KTOT) return;
    const float v = (idx / KTOT < M) ? src[idx] : 0.f;
    const bf16 hh = __float2bfloat16(v);
    h[idx] = hh;
    l[idx] = __float2bfloat16(v - __bfloat162float(hh));
}

// batched: z = blockIdx.y ; input = in + (z >> zdiv) * inStride ; out slot z
__global__ __launch_bounds__(256) void im2col3x3_bf16(
    const float* __restrict__ in, int zdiv, size_t inStride,
    bf16* __restrict__ ch, bf16* __restrict__ cl)
{
    const int z = blockIdx.y;
    const int idx = blockIdx.x * 256 + threadIdx.x;
    if (idx >= NPAD * 32) return;
    const int p = idx % NPAD, cblk = idx / NPAD;
    const float* inz = in + (size_t)(z >> zdiv) * inStride;
    bf16* oh = ch + (size_t)z * CSTR + (size_t)p * KTOT + cblk * 72;
    bf16* ol = cl + (size_t)z * CSTR + (size_t)p * KTOT + cblk * 72;
    if (p >= HW) {
        const uint4 zz = make_uint4(0, 0, 0, 0);
#pragma unroll
        for (int g = 0; g < 9; g++) { *(uint4*)(oh + g * 8) = zz; *(uint4*)(ol + g * 8) = zz; }
        return;
    }
    const int y = p / WID, x = p % WID;
#pragma unroll 1
    for (int g = 0; g < 9; g++) {
        bf16 hs[8], ls[8];
#pragma unroll
        for (int j = 0; j < 8; j++) {
            const int e = g * 8 + j, cc = e / 9, k = e - cc * 9;
            const int yy = y + k / 3 - 1, xx = x + k % 3 - 1;
            float v = 0.f;
            if (yy >= 0 && yy < WID && xx >= 0 && xx < WID)
                v = inz[(size_t)(cblk * 8 + cc) * HW + yy * WID + xx];
            hs[j] = __float2bfloat16(v);
            ls[j] = __float2bfloat16(v - __bfloat162float(hs[j]));
        }
        *(uint4*)(oh + g * 8) = make_uint4(bpack(hs[0],hs[1]), bpack(hs[2],hs[3]),
                                           bpack(hs[4],hs[5]), bpack(hs[6],hs[7]));
        *(uint4*)(ol + g * 8) = make_uint4(bpack(ls[0],ls[1]), bpack(ls[2],ls[3]),
                                           bpack(ls[4],ls[5]), bpack(ls[6],ls[7]));
    }
}

// batched deform: global z = zoff + blockIdx.y in [0,18) = bpp*9 + ap ; t = cls/reg
__global__ __launch_bounds__(256) void im2col_def_bf16(
    const float* __restrict__ ft, int t, const float* __restrict__ boxreg,
    bf16* __restrict__ ch, bf16* __restrict__ cl, int zoff)
{
    const int zl = blockIdx.y;
    const int z = zl + zoff;
    const int bpp = z / 9, ap = z % 9;
    const int nn = ap * 2 + bpp, bb = nn / 9, aa = nn % 9;
    const float aw = c_AW[aa], ah_ = c_AH[aa];
    const int idx = blockIdx.x * 256 + threadIdx.x;
    if (idx >= NPAD * 32) return;
    const int p = idx % NPAD, cblk = idx / NPAD;
    bf16* oh = ch + (size_t)zl * CSTR + (size_t)p * KTOT + cblk * 72;
    bf16* ol = cl + (size_t)zl * CSTR + (size_t)p * KTOT + cblk * 72;
    if (p >= HW) {
        const uint4 zz = make_uint4(0, 0, 0, 0);
#pragma unroll
        for (int g = 0; g < 9; g++) { *(uint4*)(oh + g * 8) = zz; *(uint4*)(ol + g * 8) = zz; }
        return;
    }
    const float* feat = ft + (size_t)(bpp * 2 + t) * FSTR;
    const float* br = boxreg + (size_t)bb * 36 * HW + (size_t)aa * 4 * HW + p;
    const int y = p / WID, x = p % WID;
    const float r0 = br[0], r1 = br[HW], r2 = br[2 * HW], r3 = br[3 * HW];
    const float whx = aw * expf(r2), why = ah_ * expf(r3);
    const float tlx = aw * r0 - 0.5f * whx, tly = ah_ * r1 - 0.5f * why;
    const float gxv[3] = {tlx, tlx + 0.5f * whx, tlx + whx};
    const float gyv[3] = {tly, tly + 0.5f * why, tly + why};
    int O00[9], O01[9], O10[9], O11[9];
    float W00[9], W01[9], W10[9], W11[9];
#pragma unroll
    for (int i = 0; i < 3; i++) {
        const float pxf = (float)x + gyv[i];
        const float x0f = floorf(pxf);
        const float lx = pxf - x0f;
        const int ix0 = (int)x0f;
        const bool vx0 = (ix0 >= 0) && (ix0 < WID), vx1 = (ix0 + 1 >= 0) && (ix0 + 1 < WID);
        const int xc0 = min(max(ix0, 0), WID - 1), xc1 = min(max(ix0 + 1, 0), WID - 1);
#pragma unroll
        for (int j = 0; j < 3; j++) {
            const int k = i * 3 + j;
            const float pyf = (float)y + gxv[j];
            const float y0f = floorf(pyf);
            const float ly = pyf - y0f;
            const int iy0 = (int)y0f;
            const bool vy0 = (iy0 >= 0) && (iy0 < WID), vy1 = (iy0 + 1 >= 0) && (iy0 + 1 < WID);
            const int yc0 = min(max(iy0, 0), WID - 1), yc1 = min(max(iy0 + 1, 0), WID - 1);
            O00[k] = yc0 * WID + xc0; O01[k] = yc0 * WID + xc1;
            O10[k] = yc1 * WID + xc0; O11[k] = yc1 * WID + xc1;
            W00[k] = (vy0 && vx0) ? (1.f - ly) * (1.f - lx) : 0.f;
            W01[k] = (vy0 && vx1) ? (1.f - ly) * lx : 0.f;
            W10[k] = (vy1 && vx0) ? ly * (1.f - lx) : 0.f;
            W11[k] = (vy1 && vx1) ? ly * lx : 0.f;
        }
    }
#pragma unroll 1
    for (int g = 0; g < 9; g++) {
        bf16 hs[8], ls[8];
#pragma unroll
        for (int j = 0; j < 8; j++) {
            const int e = g * 8 + j, cc = e / 9, k = e - cc * 9;
            const float* f = feat + (size_t)(cblk * 8 + cc) * HW;
            const float v = W00[k]*f[O00[k]] + W01[k]*f[O01[k]] + W10[k]*f[O10[k]] + W11[k]*f[O11[k]];
            hs[j] = __float2bfloat16(v);
            ls[j] = __float2bfloat16(v - __bfloat162float(hs[j]));
        }
        *(uint4*)(oh + g * 8) = make_uint4(bpack(hs[0],hs[1]), bpack(hs[2],hs[3]),
                                           bpack(hs[4],hs[5]), bpack(hs[6],hs[7]));
        *(uint4*)(ol + g * 8) = make_uint4(bpack(ls[0],ls[1]), bpack(ls[2],ls[3]),
                                           bpack(ls[4],ls[5]), bpack(ls[6],ls[7]));
    }
}

__global__ void delta_kernel(const float* __restrict__ boxreg, const float* __restrict__ refine,
                             float* __restrict__ out)
{
    const int idx = blockIdx.x * blockDim.x + threadIdx.x;
    if (idx >= 2 * 36 * HW) return;
    const int p = idx % HW, ch = (idx / HW) % 36, b = idx / (36 * HW), c = ch & 3;
    const float o1 = boxreg[((size_t)b * 36 + ch) * HW + p];
    const float o2 = refine[((size_t)b * 36 + ch) * HW + p];
    float v;
    if (c < 2) v = o1 + expf(boxreg[((size_t)b * 36 + ch + 2) * HW + p]) * o2;
    else       v = o1 + o2;
    out[idx] = v;
}

#define W_CLS   0
#define W_REG   1024
#define W_PRED  2048
#define W_DCLS  2176
#define W_DREG  2432
#define W_LOGIT 2688
#define W_REFIN 3456

extern "C" void kernel_launch(void* const* d_in, const int* in_sizes, int n_in,
                              void* d_out, int out_size)
{
    const float* x        = (const float*)d_in[0];
    const float* cls_w    = (const float*)d_in[1];
    const float* cls_b    = (const float*)d_in[2];
    const float* reg_w    = (const float*)d_in[3];
    const float* reg_b    = (const float*)d_in[4];
    const float* pred_w   = (const float*)d_in[5];
    const float* pred_b   = (const float*)d_in[6];
    const float* dcls_w   = (const float*)d_in[7];
    const float* dreg_w   = (const float*)d_in[8];
    const float* logit_w  = (const float*)d_in[9];
    const float* logit_b  = (const float*)d_in[10];
    const float* refine_w = (const float*)d_in[11];
    const float* refine_b = (const float*)d_in[12];

    bf16 *wh, *wl, *colh, *coll, *cth, *ctl, *crh, *crl;
    float *ftA, *ftB, *boxreg, *refine;
    cudaGetSymbolAddress((void**)&wh, g_wh);
    cudaGetSymbolAddress((void**)&wl, g_wl);
    cudaGetSymbolAddress((void**)&colh, g_colh);
    cudaGetSymbolAddress((void**)&coll, g_coll);
    cudaGetSymbolAddress((void**)&cth, g_cth);
    cudaGetSymbolAddress((void**)&ctl, g_ctl);
    cudaGetSymbolAddress((void**)&crh, g_crh);
    cudaGetSymbolAddress((void**)&crl, g_crl);
    cudaGetSymbolAddress((void**)&ftA, g_ftA);
    cudaGetSymbolAddress((void**)&ftB, g_ftB);
    cudaGetSymbolAddress((void**)&boxreg, g_boxreg);
    cudaGetSymbolAddress((void**)&refine, g_refine);

    cudaFuncSetAttribute(mma_gemm, cudaFuncAttributeMaxDynamicSharedMemorySize, SMEM_SZ);

    auto wsplit = [&](const float* src, int rowoff, int M, int Mp) {
        wsplit_kernel<<<(Mp * KTOT + 255) / 256, 256>>>(
            src, wh + (size_t)rowoff * KTOT, wl + (size_t)rowoff * KTOT, M, Mp);
    };
    // launches 0-3 (tower + deform weights only, so launch #5 = first mma_gemm for ncu)
    wsplit(cls_w, W_CLS, 1024, 1024);
    wsplit(reg_w, W_REG, 1024, 1024);
    wsplit(dcls_w, W_DCLS, 256, 256);
    wsplit(dreg_w, W_DREG, 256, 256);

    // ---- towers: 4 layers, 4 chains (z = b*2 + tower) batched per layer ----
    const dim3 icg(NPAD * 32 / 256, 4);
    const float* lin[4] = {x, ftA, ftB, ftA};
    float* lout[4] = {ftA, ftB, ftA, ftB};
    for (int layer = 0; layer < 4; layer++) {
        im2col3x3_bf16<<<icg, 256>>>(lin[layer], layer == 0 ? 1 : 0, FSTR, colh, coll);
        dim3 grid(NPAD / 128, 2, 4);
        mma_gemm<<<grid, 256, SMEM_SZ>>>(
            wh, wl, W_CLS + layer * 256, W_REG + layer * 256,
            colh, coll, cls_b + layer * 256, reg_b + layer * 256,
            lout[layer], FSTR, nullptr, nullptr, 256, 1 | 2 | 8, 0);
    }

    // remaining weight splits (needed from pred conv onward)
    wsplit(pred_w, W_PRED, 36, 128);
    wsplit(logit_w, W_LOGIT, 720, 768);
    wsplit(refine_w, W_REFIN, 36, 128);

    // ---- pred conv on rf chains (ftB slots 1, 3) ----
    {
        dim3 icg2(NPAD * 32 / 256, 2);
        im2col3x3_bf16<<<icg2, 256>>>(ftB + FSTR, 0, 2 * FSTR, colh, coll);
        dim3 grid(NPAD / 128, 1, 2);
        mma_gemm<<<grid, 256, SMEM_SZ>>>(
            wh, wl, W_PRED, W_PRED, colh, coll, pred_b, pred_b,
            boxreg, (size_t)36 * HW, nullptr, nullptr, 36, 1, 0);
    }

    // ---- deform: 3 batches of 6 slots per tower type ----
    {
        dim3 icg6(NPAD * 32 / 256, SLOTS);
        dim3 grid(NPAD / 128, 2, SLOTS);
        for (int base = 0; base < 18; base += SLOTS) {
            im2col_def_bf16<<<icg6, 256>>>(ftB, 0, boxreg, colh, coll, base);
            mma_gemm<<<grid, 256, SMEM_SZ>>>(
                wh, wl, W_DCLS, W_DCLS, colh, coll, nullptr, nullptr,
                nullptr, 0, cth, ctl, 256, 4, base);
        }
        for (int base = 0; base < 18; base += SLOTS) {
            im2col_def_bf16<<<icg6, 256>>>(ftB, 1, boxreg, colh, coll, base);
            mma_gemm<<<grid, 256, SMEM_SZ>>>(
                wh, wl, W_DREG, W_DREG, colh, coll, nullptr, nullptr,
                nullptr, 0, crh, crl, 256, 4, base);
        }
    }

    // ---- 1x1 heads (z = batch; cat slot stride == CSTR) ----
    float* logits_out = (float*)d_out;
    float* delta_out = logits_out + (size_t)2 * 720 * HW;
    {
        dim3 gl(NPAD / 128, 6, 2);
        mma_gemm<<<gl, 256, SMEM_SZ>>>(
            wh, wl, W_LOGIT, W_LOGIT, cth, ctl, logit_b, logit_b,
            logits_out, (size_t)720 * HW, nullptr, nullptr, 720, 1, 0);
        dim3 gr(NPAD / 128, 1, 2);
        mma_gemm<<<gr, 256, SMEM_SZ>>>(
            wh, wl, W_REFIN, W_REFIN, crh, crl, refine_b, refine_b,
            refine, (size_t)36 * HW, nullptr, nullptr, 36, 1, 0);
    }

    delta_kernel<<<(2 * 36 * HW + 255) / 256, 256>>>(boxreg, refine, delta_out);
}

// round 9
// speedup vs baseline: 1.0887x; 1.0887x over previous
#include <cuda_runtime.h>
#include <cuda_bf16.h>
#include <cstdint>
#include <cstddef>

#define HW    10000
#define WID   100
#define NPAD  10240
#define KTOT  2304
#define WROWS 3584
#define SLOTS 6
#define CSTR  ((size_t)NPAD * KTOT)   // col-slot stride (elements)
#define FSTR  ((size_t)256 * HW)      // feature-chain stride

typedef __nv_bfloat16 bf16;

__device__ bf16 g_wh[WROWS * KTOT];              // 16.5 MB
__device__ bf16 g_wl[WROWS * KTOT];
__device__ bf16 g_colh[SLOTS * CSTR];            // 283 MB
__device__ bf16 g_coll[SLOTS * CSTR];
__device__ bf16 g_cth[2 * CSTR];                 // cls cat (94 MB)
__device__ bf16 g_ctl[2 * CSTR];
__device__ bf16 g_crh[2 * CSTR];                 // reg cat
__device__ bf16 g_crl[2 * CSTR];
__device__ float g_ftA[4 * 256 * HW];            // tower ping
__device__ float g_ftB[4 * 256 * HW];            // tower pong (final: cf0,rf0,cf1,rf1)
__device__ float g_boxreg[2 * 36 * HW];
__device__ float g_refine[2 * 36 * HW];

__constant__ float c_AW[9] = {
    2.8284271247461903f, 2.0f, 1.4142135623730951f,
    3.5635948725613580f, 2.5198420997897464f, 1.7817974362806790f,
    4.4898481932374910f, 3.1748021039363988f, 2.2449240966187455f};
__constant__ float c_AH[9] = {
    1.4142135623730951f, 2.0f, 2.8284271247461903f,
    1.7817974362806790f, 2.5198420997897464f, 3.5635948725613580f,
    2.2449240966187455f, 3.1748021039363988f, 4.4898481932374910f};

__device__ __forceinline__ uint32_t smem_u32(const void* p) {
    uint32_t a;
    asm("{ .reg .u64 t; cvta.to.shared.u64 t, %1; cvt.u32.u64 %0, t; }" : "=r"(a) : "l"(p));
    return a;
}
__device__ __forceinline__ void cp16(uint32_t dst, const void* src) {
    asm volatile("cp.async.cg.shared.global [%0], [%1], 16;" :: "r"(dst), "l"(src));
}
__device__ __forceinline__ void ldmx4(uint32_t* r, uint32_t addr) {
    asm volatile("ldmatrix.sync.aligned.m8n8.x4.shared.b16 {%0,%1,%2,%3}, [%4];"
                 : "=r"(r[0]), "=r"(r[1]), "=r"(r[2]), "=r"(r[3]) : "r"(addr));
}
__device__ __forceinline__ void mma16816(float* c, const uint32_t* a, uint32_t b0, uint32_t b1) {
    asm volatile("mma.sync.aligned.m16n8k16.row.col.f32.bf16.bf16.f32 "
                 "{%0,%1,%2,%3}, {%4,%5,%6,%7}, {%8,%9}, {%0,%1,%2,%3};"
                 : "+f"(c[0]), "+f"(c[1]), "+f"(c[2]), "+f"(c[3])
                 : "r"(a[0]), "r"(a[1]), "r"(a[2]), "r"(a[3]), "r"(b0), "r"(b1));
}
__device__ __forceinline__ uint32_t bpack(bf16 a, bf16 b) {
    return (uint32_t)__bfloat16_as_ushort(a) | ((uint32_t)__bfloat16_as_ushort(b) << 16);
}
// smem tile: 128 rows x 4 chunks of 16B (BK=32), XOR-4 swizzle
__device__ __forceinline__ uint32_t sw_off(int r, int c) {
    return (uint32_t)((r * 4 + (c ^ (r & 3))) << 4);
}

#define TILE_B 8192
#define STAGE_B (4 * TILE_B)
#define NSTG 3
#define NK   72
#define SMEM_SZ (NSTG * STAGE_B)     // 96 KB -> 2 CTAs/SM

// flags: 1=bias 2=relu 4=cat-out 8=tower(z-indexed A/bias)
__global__ __launch_bounds__(256, 2) void mma_gemm(
    const bf16* __restrict__ Ah0, const bf16* __restrict__ Al0, int arowE, int arowO,
    const bf16* __restrict__ Bh0, const bf16* __restrict__ Bl0,
    const float* __restrict__ biasE, const float* __restrict__ biasO,
    float* __restrict__ outF, size_t outStride,
    bf16* __restrict__ outTh, bf16* __restrict__ outTl,
    int M, int flags, int zoff)
{
    extern __shared__ char smem[];
    const uint32_t sb = smem_u32(smem);
    const int tid = threadIdx.x, lane = tid & 31, w = tid >> 5;
    const int wm = w >> 2, wn = w & 3;
    const int m0 = blockIdx.y * 128, n0 = blockIdx.x * 128;
    const int zl = blockIdx.z;          // local z (col slot)
    const int z = zl + zoff;            // global z (cat / out index)

    const bool odd = (flags & 8) && (z & 1);
    const int arow = odd ? arowO : arowE;
    const float* bias = odd ? biasO : biasE;

    const bf16* srcs[4] = {
        Ah0 + ((size_t)arow + m0) * KTOT, Al0 + ((size_t)arow + m0) * KTOT,
        Bh0 + (size_t)zl * CSTR + (size_t)n0 * KTOT,
        Bl0 + (size_t)zl * CSTR + (size_t)n0 * KTOT};

    float acc[4][4][4];
#pragma unroll
    for (int i = 0; i < 4; i++)
#pragma unroll
        for (int j = 0; j < 4; j++)
#pragma unroll
            for (int q = 0; q < 4; q++) acc[i][j][q] = 0.f;

    const int ra = (lane & 15);
    const int ca = lane >> 4;
    const int rb = (lane & 7) + ((lane >> 4) << 3);
    const int cb = (lane >> 3) & 1;

#define LOAD_STAGE(s, k0) do { \
    _Pragma("unroll") \
    for (int t = 0; t < 4; t++) { \
        const uint32_t base = sb + (uint32_t)((s) * STAGE_B + t * TILE_B); \
        _Pragma("unroll") \
        for (int h = 0; h < 2; h++) { \
            const int q = tid + h * 256; \
            const int r = q >> 2, c = q & 3; \
            cp16(base + sw_off(r, c), srcs[t] + (size_t)r * KTOT + (k0) + c * 8); \
        } \
    } \
} while (0)

    LOAD_STAGE(0, 0);
    asm volatile("cp.async.commit_group;" ::: "memory");
    LOAD_STAGE(1, 32);
    asm volatile("cp.async.commit_group;" ::: "memory");

    for (int kc = 0; kc < NK; kc++) {
        asm volatile("cp.async.wait_group 1;" ::: "memory");
        __syncthreads();

        const uint32_t bA  = sb + (uint32_t)((kc % NSTG) * STAGE_B);
        const uint32_t bAl = bA + TILE_B;
        const uint32_t bBh = bA + 2 * TILE_B;
        const uint32_t bBl = bA + 3 * TILE_B;
#pragma unroll
        for (int kh = 0; kh < 2; kh++) {
            uint32_t fbh[2][4], fbl[2][4];
#pragma unroll
            for (int nt2 = 0; nt2 < 2; nt2++) {
                const int rr = wn * 32 + nt2 * 16 + rb;
                const int cc = kh * 2 + cb;
                ldmx4(fbh[nt2], bBh + sw_off(rr, cc));
                ldmx4(fbl[nt2], bBl + sw_off(rr, cc));
            }
#pragma unroll
            for (int mt = 0; mt < 4; mt++) {
                uint32_t fah[4], fal[4];
                const int rr = wm * 64 + mt * 16 + ra;
                const int cc = kh * 2 + ca;
                ldmx4(fah, bA  + sw_off(rr, cc));
                ldmx4(fal, bAl + sw_off(rr, cc));
#pragma unroll
                for (int nt = 0; nt < 4; nt++) {
                    const uint32_t b0h = fbh[nt >> 1][(nt & 1) * 2];
                    const uint32_t b1h = fbh[nt >> 1][(nt & 1) * 2 + 1];
                    const uint32_t b0l = fbl[nt >> 1][(nt & 1) * 2];
                    const uint32_t b1l = fbl[nt >> 1][(nt & 1) * 2 + 1];
                    mma16816(acc[mt][nt], fah, b0h, b1h);
                    mma16816(acc[mt][nt], fah, b0l, b1l);
                    mma16816(acc[mt][nt], fal, b0h, b1h);
                }
            }
        }
        if (kc + 2 < NK) LOAD_STAGE((kc + 2) % NSTG, (kc + 2) * 32);
        asm volatile("cp.async.commit_group;" ::: "memory");
    }
    __syncthreads();

    const int group = lane >> 2, tid4 = lane & 3;

    if (flags & 4) {
        const int bpp = z / 9, ap = z % 9;
        float* smf = (float*)smem;
#pragma unroll
        for (int mt = 0; mt < 4; mt++) {
#pragma unroll
            for (int nt = 0; nt < 4; nt++) {
                const int ml = wm * 64 + mt * 16 + group;
                const int nl = wn * 32 + nt * 8 + tid4 * 2;
                smf[nl * 128 + ml]           = acc[mt][nt][0];
                smf[(nl + 1) * 128 + ml]     = acc[mt][nt][1];
                smf[nl * 128 + ml + 8]       = acc[mt][nt][2];
                smf[(nl + 1) * 128 + ml + 8] = acc[mt][nt][3];
            }
        }
        __syncthreads();
        const int nl = tid >> 1, half = tid & 1;
        const size_t row_out = (size_t)(bpp * NPAD + n0 + nl) * KTOT + ap * 256 + m0 + half * 64;
        const float* row = smf + nl * 128 + half * 64;
        bf16* oh = outTh + row_out;
        bf16* ol = outTl + row_out;
#pragma unroll
        for (int g = 0; g < 8; g++) {
            bf16 hs[8], ls[8];
#pragma unroll
            for (int j = 0; j < 8; j++) {
                const float v = fmaxf(row[g * 8 + j], 0.f);
                hs[j] = __float2bfloat16(v);
                ls[j] = __float2bfloat16(v - __bfloat162float(hs[j]));
            }
            *(uint4*)(oh + g * 8) = make_uint4(bpack(hs[0],hs[1]), bpack(hs[2],hs[3]),
                                               bpack(hs[4],hs[5]), bpack(hs[6],hs[7]));
            *(uint4*)(ol + g * 8) = make_uint4(bpack(ls[0],ls[1]), bpack(ls[2],ls[3]),
                                               bpack(ls[4],ls[5]), bpack(ls[6],ls[7]));
        }
    } else {
        float* oF = outF + (size_t)z * outStride;
#pragma unroll
        for (int mt = 0; mt < 4; mt++) {
            const int mA = m0 + wm * 64 + mt * 16 + group;
            const int mB = mA + 8;
            const float bvA = ((flags & 1) && mA < M) ? bias[mA] : 0.f;
            const float bvB = ((flags & 1) && mB < M) ? bias[mB] : 0.f;
#pragma unroll
            for (int nt = 0; nt < 4; nt++) {
                const int n = n0 + wn * 32 + nt * 8 + tid4 * 2;
#pragma unroll
                for (int e = 0; e < 2; e++) {
                    if (n + e < HW) {
                        if (mA < M) {
                            float v = acc[mt][nt][e] + bvA;
                            if (flags & 2) v = fmaxf(v, 0.f);
                            oF[(size_t)mA * HW + n + e] = v;
                        }
                        if (mB < M) {
                            float v = acc[mt][nt][2 + e] + bvB;
                            if (flags & 2) v = fmaxf(v, 0.f);
                            oF[(size_t)mB * HW + n + e] = v;
                        }
                    }
                }
            }
        }
    }
#undef LOAD_STAGE
}

__global__ void wsplit_kernel(const float* __restrict__ src, bf16* __restrict__ h,
                              bf16* __restrict__ l, int M, int Mp)
{
    const int idx = blockIdx.x * blockDim.x + threadIdx.x;
    if (idx >= Mp * KTOT) return;
    const float v = (idx / KTOT < M) ? src[idx] : 0.f;
    const bf16 hh = __float2bfloat16(v);
    h[idx] = hh;
    l[idx] = __float2bfloat16(v - __bfloat162float(hh));
}

// batched: z = blockIdx.y ; input = in + (z >> zdiv) * inStride ; out slot z
__global__ __launch_bounds__(256) void im2col3x3_bf16(
    const float* __restrict__ in, int zdiv, size_t inStride,
    bf16* __restrict__ ch, bf16* __restrict__ cl)
{
    const int z = blockIdx.y;
    const int idx = blockIdx.x * 256 + threadIdx.x;
    if (idx >= NPAD * 32) return;
    const int p = idx % NPAD, cblk = idx / NPAD;
    const float* inz = in + (size_t)(z >> zdiv) * inStride;
    bf16* oh = ch + (size_t)z * CSTR + (size_t)p * KTOT + cblk * 72;
    bf16* ol = cl + (size_t)z * CSTR + (size_t)p * KTOT + cblk * 72;
    if (p >= HW) {
        const uint4 zz = make_uint4(0, 0, 0, 0);
#pragma unroll
        for (int g = 0; g < 9; g++) { *(uint4*)(oh + g * 8) = zz; *(uint4*)(ol + g * 8) = zz; }
        return;
    }
    const int y = p / WID, x = p % WID;
#pragma unroll 1
    for (int g = 0; g < 9; g++) {
        bf16 hs[8], ls[8];
#pragma unroll
        for (int j = 0; j < 8; j++) {
            const int e = g * 8 + j, cc = e / 9, k = e - cc * 9;
            const int yy = y + k / 3 - 1, xx = x + k % 3 - 1;
            float v = 0.f;
            if (yy >= 0 && yy < WID && xx >= 0 && xx < WID)
                v = inz[(size_t)(cblk * 8 + cc) * HW + yy * WID + xx];
            hs[j] = __float2bfloat16(v);
            ls[j] = __float2bfloat16(v - __bfloat162float(hs[j]));
        }
        *(uint4*)(oh + g * 8) = make_uint4(bpack(hs[0],hs[1]), bpack(hs[2],hs[3]),
                                           bpack(hs[4],hs[5]), bpack(hs[6],hs[7]));
        *(uint4*)(ol + g * 8) = make_uint4(bpack(ls[0],ls[1]), bpack(ls[2],ls[3]),
                                           bpack(ls[4],ls[5]), bpack(ls[6],ls[7]));
    }
}

// batched deform: global z = zoff + blockIdx.y ; writes LOCAL slot blockIdx.y of ch/cl
__global__ __launch_bounds__(256) void im2col_def_bf16(
    const float* __restrict__ ft, int t, const float* __restrict__ boxreg,
    bf16* __restrict__ ch, bf16* __restrict__ cl, int zoff)
{
    const int zl = blockIdx.y;
    const int z = zl + zoff;
    const int bpp = z / 9, ap = z % 9;
    const int nn = ap * 2 + bpp, bb = nn / 9, aa = nn % 9;
    const float aw = c_AW[aa], ah_ = c_AH[aa];
    const int idx = blockIdx.x * 256 + threadIdx.x;
    if (idx >= NPAD * 32) return;
    const int p = idx % NPAD, cblk = idx / NPAD;
    bf16* oh = ch + (size_t)zl * CSTR + (size_t)p * KTOT + cblk * 72;
    bf16* ol = cl + (size_t)zl * CSTR + (size_t)p * KTOT + cblk * 72;
    if (p >= HW) {
        const uint4 zz = make_uint4(0, 0, 0, 0);
#pragma unroll
        for (int g = 0; g < 9; g++) { *(uint4*)(oh + g * 8) = zz; *(uint4*)(ol + g * 8) = zz; }
        return;
    }
    const float* feat = ft + (size_t)(bpp * 2 + t) * FSTR;
    const float* br = boxreg + (size_t)bb * 36 * HW + (size_t)aa * 4 * HW + p;
    const int y = p / WID, x = p % WID;
    const float r0 = br[0], r1 = br[HW], r2 = br[2 * HW], r3 = br[3 * HW];
    const float whx = aw * expf(r2), why = ah_ * expf(r3);
    const float tlx = aw * r0 - 0.5f * whx, tly = ah_ * r1 - 0.5f * why;
    const float gxv[3] = {tlx, tlx + 0.5f * whx, tlx + whx};
    const float gyv[3] = {tly, tly + 0.5f * why, tly + why};
    int O00[9], O01[9], O10[9], O11[9];
    float W00[9], W01[9], W10[9], W11[9];
#pragma unroll
    for (int i = 0; i < 3; i++) {
        const float pxf = (float)x + gyv[i];
        const float x0f = floorf(pxf);
        const float lx = pxf - x0f;
        const int ix0 = (int)x0f;
        const bool vx0 = (ix0 >= 0) && (ix0 < WID), vx1 = (ix0 + 1 >= 0) && (ix0 + 1 < WID);
        const int xc0 = min(max(ix0, 0), WID - 1), xc1 = min(max(ix0 + 1, 0), WID - 1);
#pragma unroll
        for (int j = 0; j < 3; j++) {
            const int k = i * 3 + j;
            const float pyf = (float)y + gxv[j];
            const float y0f = floorf(pyf);
            const float ly = pyf - y0f;
            const int iy0 = (int)y0f;
            const bool vy0 = (iy0 >= 0) && (iy0 < WID), vy1 = (iy0 + 1 >= 0) && (iy0 + 1 < WID);
            const int yc0 = min(max(iy0, 0), WID - 1), yc1 = min(max(iy0 + 1, 0), WID - 1);
            O00[k] = yc0 * WID + xc0; O01[k] = yc0 * WID + xc1;
            O10[k] = yc1 * WID + xc0; O11[k] = yc1 * WID + xc1;
            W00[k] = (vy0 && vx0) ? (1.f - ly) * (1.f - lx) : 0.f;
            W01[k] = (vy0 && vx1) ? (1.f - ly) * lx : 0.f;
            W10[k] = (vy1 && vx0) ? ly * (1.f - lx) : 0.f;
            W11[k] = (vy1 && vx1) ? ly * lx : 0.f;
        }
    }
#pragma unroll 1
    for (int g = 0; g < 9; g++) {
        bf16 hs[8], ls[8];
#pragma unroll
        for (int j = 0; j < 8; j++) {
            const int e = g * 8 + j, cc = e / 9, k = e - cc * 9;
            const float* f = feat + (size_t)(cblk * 8 + cc) * HW;
            const float v = W00[k]*f[O00[k]] + W01[k]*f[O01[k]] + W10[k]*f[O10[k]] + W11[k]*f[O11[k]];
            hs[j] = __float2bfloat16(v);
            ls[j] = __float2bfloat16(v - __bfloat162float(hs[j]));
        }
        *(uint4*)(oh + g * 8) = make_uint4(bpack(hs[0],hs[1]), bpack(hs[2],hs[3]),
                                           bpack(hs[4],hs[5]), bpack(hs[6],hs[7]));
        *(uint4*)(ol + g * 8) = make_uint4(bpack(ls[0],ls[1]), bpack(ls[2],ls[3]),
                                           bpack(ls[4],ls[5]), bpack(ls[6],ls[7]));
    }
}

__global__ void delta_kernel(const float* __restrict__ boxreg, const float* __restrict__ refine,
                             float* __restrict__ out)
{
    const int idx = blockIdx.x * blockDim.x + threadIdx.x;
    if (idx >= 2 * 36 * HW) return;
    const int p = idx % HW, ch = (idx / HW) % 36, b = idx / (36 * HW), c = ch & 3;
    const float o1 = boxreg[((size_t)b * 36 + ch) * HW + p];
    const float o2 = refine[((size_t)b * 36 + ch) * HW + p];
    float v;
    if (c < 2) v = o1 + expf(boxreg[((size_t)b * 36 + ch + 2) * HW + p]) * o2;
    else       v = o1 + o2;
    out[idx] = v;
}

#define W_CLS   0
#define W_REG   1024
#define W_PRED  2048
#define W_DCLS  2176
#define W_DREG  2432
#define W_LOGIT 2688
#define W_REFIN 3456

// host-side stream/event resources (host objects only; no device memory)
static cudaStream_t s_gather = nullptr;
static cudaEvent_t s_evG[12], s_evM[12], s_evFork, s_evJoin;
static void ensure_streams() {
    if (!s_gather) {
        cudaStreamCreateWithFlags(&s_gather, cudaStreamNonBlocking);
        for (int i = 0; i < 12; i++) {
            cudaEventCreateWithFlags(&s_evG[i], cudaEventDisableTiming);
            cudaEventCreateWithFlags(&s_evM[i], cudaEventDisableTiming);
        }
        cudaEventCreateWithFlags(&s_evFork, cudaEventDisableTiming);
        cudaEventCreateWithFlags(&s_evJoin, cudaEventDisableTiming);
    }
}

extern "C" void kernel_launch(void* const* d_in, const int* in_sizes, int n_in,
                              void* d_out, int out_size)
{
    const float* x        = (const float*)d_in[0];
    const float* cls_w    = (const float*)d_in[1];
    const float* cls_b    = (const float*)d_in[2];
    const float* reg_w    = (const float*)d_in[3];
    const float* reg_b    = (const float*)d_in[4];
    const float* pred_w   = (const float*)d_in[5];
    const float* pred_b   = (const float*)d_in[6];
    const float* dcls_w   = (const float*)d_in[7];
    const float* dreg_w   = (const float*)d_in[8];
    const float* logit_w  = (const float*)d_in[9];
    const float* logit_b  = (const float*)d_in[10];
    const float* refine_w = (const float*)d_in[11];
    const float* refine_b = (const float*)d_in[12];

    bf16 *wh, *wl, *colh, *coll, *cth, *ctl, *crh, *crl;
    float *ftA, *ftB, *boxreg, *refine;
    cudaGetSymbolAddress((void**)&wh, g_wh);
    cudaGetSymbolAddress((void**)&wl, g_wl);
    cudaGetSymbolAddress((void**)&colh, g_colh);
    cudaGetSymbolAddress((void**)&coll, g_coll);
    cudaGetSymbolAddress((void**)&cth, g_cth);
    cudaGetSymbolAddress((void**)&ctl, g_ctl);
    cudaGetSymbolAddress((void**)&crh, g_crh);
    cudaGetSymbolAddress((void**)&crl, g_crl);
    cudaGetSymbolAddress((void**)&ftA, g_ftA);
    cudaGetSymbolAddress((void**)&ftB, g_ftB);
    cudaGetSymbolAddress((void**)&boxreg, g_boxreg);
    cudaGetSymbolAddress((void**)&refine, g_refine);

    cudaFuncSetAttribute(mma_gemm, cudaFuncAttributeMaxDynamicSharedMemorySize, SMEM_SZ);
    ensure_streams();

    auto wsplit = [&](const float* src, int rowoff, int M, int Mp) {
        wsplit_kernel<<<(Mp * KTOT + 255) / 256, 256>>>(
            src, wh + (size_t)rowoff * KTOT, wl + (size_t)rowoff * KTOT, M, Mp);
    };
    wsplit(cls_w, W_CLS, 1024, 1024);
    wsplit(reg_w, W_REG, 1024, 1024);
    wsplit(pred_w, W_PRED, 36, 128);
    wsplit(dcls_w, W_DCLS, 256, 256);
    wsplit(dreg_w, W_DREG, 256, 256);
    wsplit(logit_w, W_LOGIT, 720, 768);
    wsplit(refine_w, W_REFIN, 36, 128);

    // ---- towers: 4 layers, 4 chains (z = b*2 + tower) batched per layer ----
    const dim3 icg(NPAD * 32 / 256, 4);
    const float* lin[4] = {x, ftA, ftB, ftA};
    float* lout[4] = {ftA, ftB, ftA, ftB};
    for (int layer = 0; layer < 4; layer++) {
        im2col3x3_bf16<<<icg, 256>>>(lin[layer], layer == 0 ? 1 : 0, FSTR, colh, coll);
        dim3 grid(NPAD / 128, 2, 4);
        mma_gemm<<<grid, 256, SMEM_SZ>>>(
            wh, wl, W_CLS + layer * 256, W_REG + layer * 256,
            colh, coll, cls_b + layer * 256, reg_b + layer * 256,
            lout[layer], FSTR, nullptr, nullptr, 256, 1 | 2 | 8, 0);
    }

    // ---- pred conv on rf chains (ftB slots 1, 3) ----
    {
        dim3 icg2(NPAD * 32 / 256, 2);
        im2col3x3_bf16<<<icg2, 256>>>(ftB + FSTR, 0, 2 * FSTR, colh, coll);
        dim3 grid(NPAD / 128, 1, 2);
        mma_gemm<<<grid, 256, SMEM_SZ>>>(
            wh, wl, W_PRED, W_PRED, colh, coll, pred_b, pred_b,
            boxreg, (size_t)36 * HW, nullptr, nullptr, 36, 1, 0);
    }

    // ---- deform: 12 pipelined phases (3 slots each), gathers on side stream ----
    {
        cudaEventRecord(s_evFork, 0);
        cudaStreamWaitEvent(s_gather, s_evFork, 0);
        const dim3 icg3(NPAD * 32 / 256, 3);
        const dim3 grid(NPAD / 128, 2, 3);
        for (int i = 0; i < 12; i++) {
            const int t = i / 6;            // 0 = cls, 1 = reg
            const int base = (i % 6) * 3;   // global z offset
            const int half = (i & 1) * 3;   // col slot half (double buffer)
            bf16* bh = colh + (size_t)half * CSTR;
            bf16* bl = coll + (size_t)half * CSTR;
            // gather phase i (wait for GEMM i-2 which last read this half)
            if (i >= 2) cudaStreamWaitEvent(s_gather, s_evM[i - 2], 0);
            im2col_def_bf16<<<icg3, 256, 0, s_gather>>>(ftB, t, boxreg, bh, bl, base);
            cudaEventRecord(s_evG[i], s_gather);
            // GEMM phase i on main stream
            cudaStreamWaitEvent(0, s_evG[i], 0);
            mma_gemm<<<grid, 256, SMEM_SZ>>>(
                wh, wl, t == 0 ? W_DCLS : W_DREG, t == 0 ? W_DCLS : W_DREG,
                bh, bl, nullptr, nullptr, nullptr, 0,
                t == 0 ? cth : crh, t == 0 ? ctl : crl, 256, 4, base);
            cudaEventRecord(s_evM[i], 0);
        }
        cudaEventRecord(s_evJoin, s_gather);
        cudaStreamWaitEvent(0, s_evJoin, 0);
    }

    // ---- 1x1 heads (z = batch; cat slot stride == CSTR) ----
    float* logits_out = (float*)d_out;
    float* delta_out = logits_out + (size_t)2 * 720 * HW;
    {
        dim3 gl(NPAD / 128, 6, 2);
        mma_gemm<<<gl, 256, SMEM_SZ>>>(
            wh, wl, W_LOGIT, W_LOGIT, cth, ctl, logit_b, logit_b,
            logits_out, (size_t)720 * HW, nullptr, nullptr, 720, 1, 0);
        dim3 gr(NPAD / 128, 1, 2);
        mma_gemm<<<gr, 256, SMEM_SZ>>>(
            wh, wl, W_REFIN, W_REFIN, crh, crl, refine_b, refine_b,
            refine, (size_t)36 * HW, nullptr, nullptr, 36, 1, 0);
    }

    delta_kernel<<<(2 * 36 * HW + 255) / 256, 256>>>(boxreg, refine, delta_out);
}